// round 17
// baseline (speedup 1.0000x reference)
#include <cuda_runtime.h>
#include <cstdint>

// sbvr decode:
//   out[g*16 + l] = sum_s coeff_cache[coeff_idx[g]][s] * ((bvr[g][s] >> l) & 1)
// G = 4,194,304 groups, S = 4, L = 16.
//
// R16 -> R17: carry the software pipeline ACROSS tile boundaries. Blocks now
// own NT=4 consecutive tiles (32 iterations) and pay the ~1500cyc idx->gather
// fill ONCE instead of once per 8 iterations: rolling 8-slot buffers with
// static indices; prefetches near a tile's end target the next tile via
// compile-time +TILE offsets (one loop-invariant guard); pointers bump by
// constants per tile. Grid 2048 (~2.3 waves). Everything else = R16:
// ITER=8, PF idx/bvr/gather = 4/2/2, pipe-balanced asm decode, (256,6).

static constexpr unsigned QT_TOTAL = 16u * 1024u * 1024u;  // 4M groups * 4 quarters
static constexpr int      BLOCK    = 256;
static constexpr int      ITER     = 8;                    // iterations per tile
static constexpr int      NT       = 4;                    // tiles per block
static constexpr int      PF_I     = 4;                    // idx prefetch distance
static constexpr int      PF_W     = 2;                    // bvr prefetch distance
static constexpr int      PF_C     = 2;                    // gather prefetch distance
static constexpr unsigned BLOCKS   = QT_TOTAL / (BLOCK * ITER * NT);  // 2048
static constexpr int      GSTRIDE  = BLOCK / 4;            // 64 groups per iteration
static constexpr int      TILE_G   = GSTRIDE * ITER;       // 512 groups per tile
static constexpr int      TILE_QT  = BLOCK * ITER;         // 2048 quarters per tile

// Pipe-balanced decode: lop3 with predicate output (ALU; AND+test in one op)
// feeding predicated add.f32 (FMA pipe). Exact fp32 -> rel_err 0.
__device__ __forceinline__ float4 decode_quarter(int4 w, float4 c, unsigned m0)
{
    float4 r;
    asm(
    "{\n\t"
    ".reg .pred q, p0, p1, p2, p3;\n\t"
    ".reg .b32  t, m1, m2, m3;\n\t"
    "setp.ne.u32 q, %4, %4;\n\t"
    "shl.b32 m1, %8, 1;\n\t"
    "shl.b32 m2, %8, 2;\n\t"
    "shl.b32 m3, %8, 3;\n\t"
    // ---- element 0 ----
    "lop3.or.b32 t|p0, %4, %8, %4, 0xC0, q;\n\t"
    "lop3.or.b32 t|p1, %5, %8, %5, 0xC0, q;\n\t"
    "lop3.or.b32 t|p2, %6, %8, %6, 0xC0, q;\n\t"
    "lop3.or.b32 t|p3, %7, %8, %7, 0xC0, q;\n\t"
    "selp.f32 %0, %9, 0f00000000, p0;\n\t"
    "@p1 add.rn.f32 %0, %0, %10;\n\t"
    "@p2 add.rn.f32 %0, %0, %11;\n\t"
    "@p3 add.rn.f32 %0, %0, %12;\n\t"
    // ---- element 1 ----
    "lop3.or.b32 t|p0, %4, m1, %4, 0xC0, q;\n\t"
    "lop3.or.b32 t|p1, %5, m1, %5, 0xC0, q;\n\t"
    "lop3.or.b32 t|p2, %6, m1, %6, 0xC0, q;\n\t"
    "lop3.or.b32 t|p3, %7, m1, %7, 0xC0, q;\n\t"
    "selp.f32 %1, %9, 0f00000000, p0;\n\t"
    "@p1 add.rn.f32 %1, %1, %10;\n\t"
    "@p2 add.rn.f32 %1, %1, %11;\n\t"
    "@p3 add.rn.f32 %1, %1, %12;\n\t"
    // ---- element 2 ----
    "lop3.or.b32 t|p0, %4, m2, %4, 0xC0, q;\n\t"
    "lop3.or.b32 t|p1, %5, m2, %5, 0xC0, q;\n\t"
    "lop3.or.b32 t|p2, %6, m2, %6, 0xC0, q;\n\t"
    "lop3.or.b32 t|p3, %7, m2, %7, 0xC0, q;\n\t"
    "selp.f32 %2, %9, 0f00000000, p0;\n\t"
    "@p1 add.rn.f32 %2, %2, %10;\n\t"
    "@p2 add.rn.f32 %2, %2, %11;\n\t"
    "@p3 add.rn.f32 %2, %2, %12;\n\t"
    // ---- element 3 ----
    "lop3.or.b32 t|p0, %4, m3, %4, 0xC0, q;\n\t"
    "lop3.or.b32 t|p1, %5, m3, %5, 0xC0, q;\n\t"
    "lop3.or.b32 t|p2, %6, m3, %6, 0xC0, q;\n\t"
    "lop3.or.b32 t|p3, %7, m3, %7, 0xC0, q;\n\t"
    "selp.f32 %3, %9, 0f00000000, p0;\n\t"
    "@p1 add.rn.f32 %3, %3, %10;\n\t"
    "@p2 add.rn.f32 %3, %3, %11;\n\t"
    "@p3 add.rn.f32 %3, %3, %12;\n\t"
    "}\n\t"
    : "=f"(r.x), "=f"(r.y), "=f"(r.z), "=f"(r.w)
    : "r"(w.x), "r"(w.y), "r"(w.z), "r"(w.w),
      "r"(m0),
      "f"(c.x), "f"(c.y), "f"(c.z), "f"(c.w));
    return r;
}

__global__ __launch_bounds__(BLOCK, 6) void sbvr_kernel(
    const float4* __restrict__ coeff_cache,   // [65536] rows of 4 floats
    const int*    __restrict__ coeff_idx,     // [G]
    const int4*   __restrict__ bvr,           // [G]
    float4*       __restrict__ out)           // [4*G]
{
    unsigned t = blockIdx.x * (unsigned)(TILE_QT * NT) + threadIdx.x;
    unsigned g = t >> 2;

    const int*  ip = coeff_idx + g;
    const int4* wp = bvr + g;
    float4*     op = out + t;

    unsigned m0 = 1u << ((t & 3u) * 4u);   // invariant over all iterations

    // Rolling 8-slot pipeline buffers; all indices compile-time static.
    int    ci[ITER];
    int4   w [ITER];
    float4 c [ITER];

    // Prologue: fill streams to their distances (tile 0, offsets < ITER).
    #pragma unroll
    for (int i = 0; i < PF_I; i++)
        ci[i] = __ldcs(ip + i * GSTRIDE);
    #pragma unroll
    for (int i = 0; i < PF_W; i++)
        w[i] = __ldcs(wp + i * GSTRIDE);
    #pragma unroll
    for (int i = 0; i < PF_C; i++)
        c[i] = __ldcg(coeff_cache + ci[i]);

    for (int tile = 0; tile < NT; tile++) {
        bool more = (tile + 1 < NT);          // loop-invariant guard
        #pragma unroll
        for (int i = 0; i < ITER; i++) {
            // idx prefetch, distance 4 (wraps into next tile near the end)
            if (i + PF_I < ITER)
                ci[i + PF_I] = __ldcs(ip + (i + PF_I) * GSTRIDE);
            else if (more)
                ci[(i + PF_I) & 7] = __ldcs(ip + (i + PF_I - ITER) * GSTRIDE + TILE_G);
            // bvr prefetch, distance 2
            if (i + PF_W < ITER)
                w[i + PF_W] = __ldcs(wp + (i + PF_W) * GSTRIDE);
            else if (more)
                w[(i + PF_W) & 7] = __ldcs(wp + (i + PF_W - ITER) * GSTRIDE + TILE_G);
            // gather prefetch, distance 2 (idx slot already holds the right value)
            if (i + PF_C < ITER)
                c[i + PF_C] = __ldcg(coeff_cache + ci[i + PF_C]);
            else if (more)
                c[(i + PF_C) & 7] = __ldcg(coeff_cache + ci[(i + PF_C) & 7]);

            float4 r = decode_quarter(w[i], c[i], m0);
            __stcs(op + i * BLOCK, r);
        }
        ip += TILE_G;
        wp += TILE_G;
        op += TILE_QT;
    }
}

extern "C" void kernel_launch(void* const* d_in, const int* in_sizes, int n_in,
                              void* d_out, int out_size)
{
    const float4* coeff_cache = (const float4*)d_in[0];  // [65536,4] f32
    const int*    coeff_idx   = (const int*)d_in[1];     // [G] i32
    const int4*   bvr         = (const int4*)d_in[2];    // [G,4] i32
    float4*       out         = (float4*)d_out;          // [8192,8192] f32

    (void)in_sizes; (void)n_in; (void)out_size;

    sbvr_kernel<<<BLOCKS, BLOCK>>>(coeff_cache, coeff_idx, bvr, out);
}